// round 7
// baseline (speedup 1.0000x reference)
#include <cuda_runtime.h>
#include <cuda_bf16.h>

#define N_NODES 4096
#define IN_DIM  256
#define HID_DIM 128
#define MLP_W   16
#define MAXNNZ  256
#define GEMM_BLOCKS 128          /* 4096/32 */

// Scratch (static device globals — no allocation). Zero-initialized at load;
// g_csfx is re-zeroed by agg2 at the end of every replay (invariant: each
// kernel_launch call starts and ends with g_csfx == 0).
// NOTE: arrays that are ever accessed through float2/float4 casts MUST carry
// explicit 16B alignment — type alignment of float[] is only 4B and linker
// placement shifts between builds (this caused the R6 misaligned-address).
__device__ int                              g_col[N_NODES * MAXNNZ];
__device__ float                            g_w[N_NODES * MAXNNZ];
__device__ int                              g_nnz[N_NODES];
__device__ float                            g_rs[N_NODES];
__device__ unsigned long long               g_csfx[N_NODES];
__device__ __align__(16) float              g_P[N_NODES * HID_DIM];   // x @ W1
__device__ __align__(16) float              g_z[N_NODES * 2];

#define FX_TO_F 9.094947017729282e-13f   /* 2^-40 */

// ---------------------------------------------------------------------------
// Fused phase 1: blocks [0,128) do the dense GEMM P = x@W1 (FMA-bound);
// blocks [128, 128+4096) each build one CSR row from adj (memory-bound).
// Co-residency overlaps the two bottlenecks.
__global__ __launch_bounds__(256) void fused1_kernel(
    const float* __restrict__ x,
    const float* __restrict__ W1,
    const float* __restrict__ adj,
    const float* __restrict__ xdeg,
    const float* __restrict__ ydeg,
    const float* __restrict__ We1,
    const float* __restrict__ be1,
    const float* __restrict__ We2,
    const float* __restrict__ be2)
{
    const int t = threadIdx.x;

    if (blockIdx.x < GEMM_BLOCKS) {
        // ================= GEMM branch: P = x @ W1 =================
        __shared__ __align__(16) float sx[32][32];       // [r][k]
        __shared__ __align__(16) float swt[32][HID_DIM]; // [k][c]

        const int row0 = blockIdx.x * 32;
        const int tx   = t & 31;
        const int ty   = t >> 5;

        float acc[4][4] = {};

        for (int kt = 0; kt < IN_DIM; kt += 32) {
            {
                const int r  = t >> 3;
                const int k4 = (t & 7) * 4;
                const float4 v = *(const float4*)&x[(long)(row0 + r) * IN_DIM + kt + k4];
                sx[r][k4]     = v.x; sx[r][k4 + 1] = v.y;
                sx[r][k4 + 2] = v.z; sx[r][k4 + 3] = v.w;
            }
            {
                const int kk = t >> 5;
                const int c4 = (t & 31) * 4;
#pragma unroll
                for (int q = 0; q < 4; q++) {
                    const int k = kk + q * 8;
                    *(float4*)&swt[k][c4] =
                        *(const float4*)&W1[(long)(kt + k) * HID_DIM + c4];
                }
            }
            __syncthreads();

#pragma unroll
            for (int k = 0; k < 32; k++) {
                const float4 wv = *(const float4*)&swt[k][tx * 4];
                const float a0 = sx[ty * 4 + 0][k];
                const float a1 = sx[ty * 4 + 1][k];
                const float a2 = sx[ty * 4 + 2][k];
                const float a3 = sx[ty * 4 + 3][k];
                acc[0][0] = fmaf(a0, wv.x, acc[0][0]);
                acc[0][1] = fmaf(a0, wv.y, acc[0][1]);
                acc[0][2] = fmaf(a0, wv.z, acc[0][2]);
                acc[0][3] = fmaf(a0, wv.w, acc[0][3]);
                acc[1][0] = fmaf(a1, wv.x, acc[1][0]);
                acc[1][1] = fmaf(a1, wv.y, acc[1][1]);
                acc[1][2] = fmaf(a1, wv.z, acc[1][2]);
                acc[1][3] = fmaf(a1, wv.w, acc[1][3]);
                acc[2][0] = fmaf(a2, wv.x, acc[2][0]);
                acc[2][1] = fmaf(a2, wv.y, acc[2][1]);
                acc[2][2] = fmaf(a2, wv.z, acc[2][2]);
                acc[2][3] = fmaf(a2, wv.w, acc[2][3]);
                acc[3][0] = fmaf(a3, wv.x, acc[3][0]);
                acc[3][1] = fmaf(a3, wv.y, acc[3][1]);
                acc[3][2] = fmaf(a3, wv.z, acc[3][2]);
                acc[3][3] = fmaf(a3, wv.w, acc[3][3]);
            }
            __syncthreads();
        }

#pragma unroll
        for (int j = 0; j < 4; j++) {
            float4 v = make_float4(acc[j][0], acc[j][1], acc[j][2], acc[j][3]);
            *(float4*)&g_P[(long)(row0 + ty * 4 + j) * HID_DIM + tx * 4] = v;
        }
        return;
    }

    // ================= build branch: one CSR row per block =================
    const int row  = blockIdx.x - GEMM_BLOCKS;
    const int wid  = t >> 5;
    const int lane = t & 31;

    __shared__ float c0[MLP_W], c2[MLP_W], dd[MLP_W], spre[MLP_W];
    __shared__ float sc1[MLP_W], scb[MLP_W];
    __shared__ float sdb;
    __shared__ int   swcnt[8], swoff[8], stot;
    __shared__ float sgs[8];

    if (t < MLP_W) {
        c0[t]  = We1[t];                 // We1[0][w]  (feat = adj value)
        sc1[t] = We1[MLP_W + t];         // We1[1][w]  (feat = row degree)
        c2[t]  = We1[2 * MLP_W + t];     // We1[2][w]  (feat = col degree)
        scb[t] = be1[t];
        dd[t]  = We2[t * 2 + 1] - We2[t * 2 + 0];
    }
    if (t == 0) sdb = be2[1] - be2[0];

    const float4* arow4 = (const float4*)(adj + (long)row * N_NODES);
    const float   dr    = xdeg[(long)row * N_NODES];   // deg_row[row]

    // Front-batched streaming loads (adj is read-once: bypass L2 persistence)
    float4 v4[4];
#pragma unroll
    for (int s = 0; s < 4; s++) v4[s] = __ldcs(&arow4[s * 256 + t]);

    // Nibble nz masks + warp scans (register-only)
    int nib[4], lbase[4], wtot[4];
    int wcnt = 0;
#pragma unroll
    for (int s = 0; s < 4; s++) {
        const float4 v = v4[s];
        int nb = (v.x != 0.0f ? 1 : 0) | (v.y != 0.0f ? 2 : 0)
               | (v.z != 0.0f ? 4 : 0) | (v.w != 0.0f ? 8 : 0);
        nib[s] = nb;
        int cnt = __popc(nb);
        int pre = cnt;
#pragma unroll
        for (int off = 1; off < 32; off <<= 1) {
            int n = __shfl_up_sync(0xffffffffu, pre, off);
            if (lane >= off) pre += n;
        }
        lbase[s] = pre - cnt;
        wtot[s]  = __shfl_sync(0xffffffffu, pre, 31);
        wcnt    += wtot[s];
    }
    if (lane == 0) swcnt[wid] = wcnt;
    __syncthreads();

    if (t < MLP_W)
        spre[t] = fmaf(dr, sc1[t], scb[t]);
    if (t < 8) {
        int acc = 0;
        for (int i = 0; i < 8; i++) {
            if (i == t) swoff[t] = acc;
            acc += swcnt[i];
        }
        if (t == 0) stot = acc;
    }
    __syncthreads();

    const int wbase = swoff[wid];

    int   running = 0;
    float gs = 0.0f;
#pragma unroll
    for (int s = 0; s < 4; s++) {
        const int nb = nib[s];
        if (nb) {
            const float va[4] = { v4[s].x, v4[s].y, v4[s].z, v4[s].w };
            int rank = 0;
#pragma unroll
            for (int b = 0; b < 4; b++) {
                if (nb & (1 << b)) {
                    const int   j   = s * 1024 + t * 4 + b;
                    const float val = va[b];
                    const float dc  = ydeg[j];
                    float l = 0.0f;
#pragma unroll
                    for (int w = 0; w < MLP_W; w++) {
                        float h = fmaf(val, c0[w], fmaf(dc, c2[w], spre[w]));
                        h = fmaxf(h, 0.0f);
                        l = fmaf(h, dd[w], l);
                    }
                    l += sdb;
                    // softmax(...)[1] == sigmoid(l1-l0); weight = adj * gate
                    const float wgt = val / (1.0f + __expf(-l));
                    gs += wgt;
                    const int pos = wbase + running + lbase[s] + rank;
                    rank++;
                    if (pos < MAXNNZ) {
                        g_col[(long)row * MAXNNZ + pos] = j;
                        g_w  [(long)row * MAXNNZ + pos] = wgt;
                    }
                    atomicAdd(&g_csfx[j],
                              (unsigned long long)(wgt * 1099511627776.0f));
                }
            }
        }
        running += wtot[s];
    }

#pragma unroll
    for (int off = 16; off > 0; off >>= 1)
        gs += __shfl_xor_sync(0xffffffffu, gs, off);
    if (lane == 0) sgs[wid] = gs;
    __syncthreads();
    if (t == 0) {
        float r = 0.0f;
        for (int i = 0; i < 8; i++) r += sgs[i];
        g_rs[row]  = 1.0f + r;                       // + self loop
        g_nnz[row] = (stot < MAXNNZ) ? stot : MAXNNZ;
    }
}

// ---------------------------------------------------------------------------
// Fused: hid_row = An@P + rw*P + b1, immediately reduced against W2 -> z_row.
// Writes the fully-normalized edge weight back to g_w for agg2.
__global__ __launch_bounds__(128) void agg1z_kernel(
    const float* __restrict__ b1,
    const float* __restrict__ W2,
    const float* __restrict__ rw)
{
    const int row = blockIdx.x;
    const int t   = threadIdx.x;

    __shared__ int   sc[MAXNNZ];
    __shared__ float sw[MAXNNZ];
    __shared__ float s0[4], s1[4];

    const int   nnz = g_nnz[row];
    const float dri = rsqrtf(g_rs[row]);
    for (int k = t; k < nnz; k += 128) {
        const int c = g_col[(long)row * MAXNNZ + k];
        sc[k] = c;
        const float cs = 1.0f + (float)g_csfx[c] * FX_TO_F;
        const float wf = g_w[(long)row * MAXNNZ + k] * dri * rsqrtf(cs);
        sw[k] = wf;
        g_w[(long)row * MAXNNZ + k] = wf;   // writeback for agg2
    }
    __syncthreads();

    const float dcr  = rsqrtf(1.0f + (float)g_csfx[row] * FX_TO_F);
    const float diag = dri * dcr + rw[0];

    float acc = fmaf(diag, g_P[(long)row * HID_DIM + t], b1[t]);
    for (int e = 0; e < nnz; e++)
        acc = fmaf(sw[e], g_P[(long)sc[e] * HID_DIM + t], acc);

    // z_row = hid_row @ W2 (deterministic reduction)
    float r0 = acc * W2[t * 2 + 0];
    float r1 = acc * W2[t * 2 + 1];
#pragma unroll
    for (int off = 16; off > 0; off >>= 1) {
        r0 += __shfl_xor_sync(0xffffffffu, r0, off);
        r1 += __shfl_xor_sync(0xffffffffu, r1, off);
    }
    if ((t & 31) == 0) { s0[t >> 5] = r0; s1[t >> 5] = r1; }
    __syncthreads();
    if (t == 0)
        g_z[row * 2 + 0] = s0[0] + s0[1] + s0[2] + s0[3];
    else if (t == 1)
        g_z[row * 2 + 1] = s1[0] + s1[1] + s1[2] + s1[3];
}

// ---------------------------------------------------------------------------
// out = An@z + rw*z + b2. One warp per row; weights pre-normalized by agg1z.
// Software-pipelined col/weight loads to break the LDG->LDG dependence chain.
// Also re-zeroes g_csfx[row] after its last read (invariant for next replay).
__global__ __launch_bounds__(256) void agg2_kernel(
    const float* __restrict__ b2,
    const float* __restrict__ rw,
    float* __restrict__ out)
{
    const int row  = blockIdx.x * 8 + (threadIdx.x >> 5);
    const int lane = threadIdx.x & 31;

    const int nnz = g_nnz[row];
    const float2* z2 = (const float2*)g_z;
    const long base = (long)row * MAXNNZ;

    float a0 = 0.0f, a1 = 0.0f;
    int e = lane;
    if (e < nnz) {
        int   c0 = g_col[base + e];
        float w0 = g_w[base + e];
        while (e + 32 < nnz) {
            const int   c1 = g_col[base + e + 32];
            const float w1 = g_w[base + e + 32];
            const float2 z = z2[c0];
            a0 = fmaf(w0, z.x, a0);
            a1 = fmaf(w0, z.y, a1);
            c0 = c1; w0 = w1; e += 32;
        }
        const float2 z = z2[c0];
        a0 = fmaf(w0, z.x, a0);
        a1 = fmaf(w0, z.y, a1);
    }
#pragma unroll
    for (int off = 16; off > 0; off >>= 1) {
        a0 += __shfl_xor_sync(0xffffffffu, a0, off);
        a1 += __shfl_xor_sync(0xffffffffu, a1, off);
    }
    if (lane == 0) {
        const float dri  = rsqrtf(g_rs[row]);
        const float dcr  = rsqrtf(1.0f + (float)g_csfx[row] * FX_TO_F);
        const float diag = dri * dcr + rw[0];
        const float2 zr  = z2[row];
        out[row * 2 + 0] = a0 + diag * zr.x + b2[0];
        out[row * 2 + 1] = a1 + diag * zr.y + b2[1];
        g_csfx[row] = 0ull;          // restore invariant for the next replay
    }
}

// ---------------------------------------------------------------------------
extern "C" void kernel_launch(void* const* d_in, const int* in_sizes, int n_in,
                              void* d_out, int out_size)
{
    const float* x    = (const float*)d_in[0];
    const float* adj  = (const float*)d_in[1];
    const float* xdeg = (const float*)d_in[2];
    const float* ydeg = (const float*)d_in[3];
    const float* We1  = (const float*)d_in[4];
    const float* be1  = (const float*)d_in[5];
    const float* We2  = (const float*)d_in[6];
    const float* be2  = (const float*)d_in[7];
    const float* W1   = (const float*)d_in[8];
    const float* b1   = (const float*)d_in[9];
    const float* W2   = (const float*)d_in[10];
    const float* b2   = (const float*)d_in[11];
    const float* rw   = (const float*)d_in[12];
    float* out        = (float*)d_out;

    fused1_kernel<<<GEMM_BLOCKS + N_NODES, 256>>>(x, W1, adj, xdeg, ydeg,
                                                  We1, be1, We2, be2);
    agg1z_kernel <<<N_NODES, 128>>>(b1, W2, rw);
    agg2_kernel  <<<N_NODES / 8, 256>>>(b2, rw, out);
}